// round 3
// baseline (speedup 1.0000x reference)
#include <cuda_runtime.h>
#include <math.h>

#define N_I 100000
#define N_O 50000
#define FD 32
#define EAD 8
#define NE 100000

// Scratch (allocation-free): accumulators, reused in-place as h after root+sigmoid.
__device__ __align__(16) float g_acc_i[N_I * FD];   // layer-1 indivi agg -> h_indivi
__device__ __align__(16) float g_acc_o[N_O * FD];   // layer-1 org agg    -> h_org
__device__ __align__(16) float g_acc2[N_I];         // layer-2 agg

__device__ __forceinline__ float sigmoidf(float v) {
    return 1.0f / (1.0f + expf(-v));
}

// ---- packed fp32x2 helpers (Blackwell FFMA2 via PTX) ----------------------
__device__ __forceinline__ unsigned long long pack2(float lo, float hi) {
    unsigned long long r;
    asm("mov.b64 %0, {%1, %2};" : "=l"(r) : "f"(lo), "f"(hi));
    return r;
}
__device__ __forceinline__ float2 unpack2(unsigned long long v) {
    float2 f;
    asm("mov.b64 {%0, %1}, %2;" : "=f"(f.x), "=f"(f.y) : "l"(v));
    return f;
}
__device__ __forceinline__ unsigned long long fma2(unsigned long long a,
                                                   unsigned long long b,
                                                   unsigned long long c) {
    unsigned long long d;
    asm("fma.rn.f32x2 %0, %1, %2, %3;" : "=l"(d) : "l"(a), "l"(b), "l"(c));
    return d;
}

// ---------------------------------------------------------------------------
// Zero all accumulators (float4 grid-stride)
// ---------------------------------------------------------------------------
__global__ void zero_kernel() {
    const float4 z = make_float4(0.f, 0.f, 0.f, 0.f);
    int idx = blockIdx.x * blockDim.x + threadIdx.x;
    int stride = gridDim.x * blockDim.x;
    for (int i = idx; i < N_I * FD / 4; i += stride) ((float4*)g_acc_i)[i] = z;
    for (int i = idx; i < N_O * FD / 4; i += stride) ((float4*)g_acc_o)[i] = z;
    for (int i = idx; i < N_I / 4;      i += stride) ((float4*)g_acc2)[i] = z;
}

// ---------------------------------------------------------------------------
// Fused layer-1 edge kernel, f32x2 version, both relations in one grid.
//   msg[e,o] = sum_i x_src[src[e],i] * (bm[i,o] + sum_a e[a]*Wm[a,i,o])
// Layout: warp = 2 half-warps; half h handles edges eb+2h+{0,1};
// lane p=lane&15 covers channel pair (2p, 2p+1) as one f32x2.
// Wm/bm staged in shared, read as LDS.64 pairs. Edge attrs prepacked as
// splat pairs in registers. Scatter via vector atomicAdd(float2).
// ---------------------------------------------------------------------------
#define EDGE_BLK_PER_REL 3125   // 100000 edges / (8 warps * 4 edges)

__global__ __launch_bounds__(256) void edge_msg_fused(
    const float* __restrict__ xA, const int* __restrict__ srcA,
    const int* __restrict__ dstA, const float* __restrict__ eaA,
    const float* __restrict__ WmA, const float* __restrict__ bmA,
    const float* __restrict__ xB, const int* __restrict__ srcB,
    const int* __restrict__ dstB, const float* __restrict__ eaB,
    const float* __restrict__ WmB, const float* __restrict__ bmB)
{
    __shared__ float sWm[EAD * FD * FD];   // 32 KB
    __shared__ float sbm[FD * FD];         // 4 KB

    const int rel = (blockIdx.x >= EDGE_BLK_PER_REL) ? 1 : 0;
    const int blk = blockIdx.x - rel * EDGE_BLK_PER_REL;

    const float* __restrict__ x   = rel ? xB   : xA;
    const int*   __restrict__ src = rel ? srcB : srcA;
    const int*   __restrict__ dst = rel ? dstB : dstA;
    const float* __restrict__ ea  = rel ? eaB  : eaA;
    const float* __restrict__ Wm  = rel ? WmB  : WmA;
    const float* __restrict__ bm  = rel ? bmB  : bmA;
    float* acc = rel ? g_acc_o : g_acc_i;

    const int t = threadIdx.x;
    #pragma unroll
    for (int k = 0; k < 8; k++)
        ((float4*)sWm)[t + k * 256] = ((const float4*)Wm)[t + k * 256];
    ((float4*)sbm)[t] = ((const float4*)bm)[t];
    __syncthreads();

    const int lane = t & 31;
    const int warp = t >> 5;
    const int h = lane >> 4;      // half-warp id
    const int p = lane & 15;      // channel pair id (channels 2p, 2p+1)

    const int gw = blk * 8 + warp;          // global warp id within relation
    const int e0 = gw * 4 + 2 * h;          // this half's first edge
    const int e1 = e0 + 1;
    if (e0 >= NE) return;
    const bool v1 = (e1 < NE);

    const int s0 = src[e0];
    const int s1 = v1 ? src[e1] : 0;
    const int d0 = dst[e0];
    const int d1 = v1 ? dst[e1] : -1;

    // gather source rows: channel pair per lane, coalesced 128B per row
    const float2 xr0 = ((const float2*)x)[s0 * 16 + p];
    const float2 xr1 = ((const float2*)x)[s1 * 16 + p];

    // edge attrs -> splat f32x2 pairs (once per edge, amortized over i-loop)
    float ev0 = (p < EAD) ? ea[e0 * EAD + p] : 0.f;
    float ev1 = (v1 && p < EAD) ? ea[e1 * EAD + p] : 0.f;
    unsigned long long er0[EAD], er1[EAD];
    #pragma unroll
    for (int a = 0; a < EAD; a++) {
        float a0 = __shfl_sync(0xffffffffu, ev0, a, 16);
        float a1 = __shfl_sync(0xffffffffu, ev1, a, 16);
        er0[a] = pack2(a0, a0);
        er1[a] = pack2(a1, a1);
    }

    const unsigned long long* sWm64 = (const unsigned long long*)sWm;
    const unsigned long long* sbm64 = (const unsigned long long*)sbm;

    unsigned long long msg0 = 0ULL, msg1 = 0ULL;

    #pragma unroll
    for (int i = 0; i < FD; i++) {
        unsigned long long w0 = sbm64[i * 16 + p];
        unsigned long long w1 = w0;
        #pragma unroll
        for (int a = 0; a < EAD; a++) {
            unsigned long long wm = sWm64[(a * FD + i) * 16 + p];
            w0 = fma2(er0[a], wm, w0);
            w1 = fma2(er1[a], wm, w1);
        }
        // broadcast x_i within each half-warp (compile-time lane select)
        float xv0 = __shfl_sync(0xffffffffu, (i & 1) ? xr0.y : xr0.x, i >> 1, 16);
        float xv1 = __shfl_sync(0xffffffffu, (i & 1) ? xr1.y : xr1.x, i >> 1, 16);
        msg0 = fma2(pack2(xv0, xv0), w0, msg0);
        msg1 = fma2(pack2(xv1, xv1), w1, msg1);
    }

    atomicAdd(((float2*)(acc + (size_t)d0 * FD)) + p, unpack2(msg0));
    if (d1 >= 0)
        atomicAdd(((float2*)(acc + (size_t)d1 * FD)) + p, unpack2(msg1));
}

// ---------------------------------------------------------------------------
// Fused root kernel (both node types), f32x2 + coalesced smem staging:
//   acc[n,:] = sigmoid(acc[n,:] + x[n,:] @ Wr + b)
// ---------------------------------------------------------------------------
#define ROOT_BLK_I ((N_I + 255) / 256)   // 391
#define ROOT_BLK_O ((N_O + 255) / 256)   // 196

__global__ __launch_bounds__(256) void root_fused(
    const float* __restrict__ xI, const float* __restrict__ WrI, const float* __restrict__ bI,
    const float* __restrict__ xO, const float* __restrict__ WrO, const float* __restrict__ bO)
{
    __shared__ float sW[FD * FD];      // 4 KB
    __shared__ float sb[FD];
    __shared__ float sx[256 * 33];     // 33.8 KB staging (pad 33 -> conflict-free)

    const int rel = (blockIdx.x >= ROOT_BLK_I) ? 1 : 0;
    const float* __restrict__ x  = rel ? xO  : xI;
    const float* __restrict__ Wr = rel ? WrO : WrI;
    const float* __restrict__ b  = rel ? bO  : bI;
    float* acc = rel ? g_acc_o : g_acc_i;
    const int N = rel ? N_O : N_I;
    const int base = (rel ? (blockIdx.x - ROOT_BLK_I) : blockIdx.x) * 256;

    const int t = threadIdx.x;
    ((float4*)sW)[t] = ((const float4*)Wr)[t];
    if (t < FD) sb[t] = b[t];

    const int nelem = min(256, N - base) * FD;   // valid floats in this tile
    const size_t gbase = (size_t)base * FD;

    // stage x tile, coalesced
    #pragma unroll
    for (int k = 0; k < 32; k++) {
        int j = k * 256 + t;
        if (j < nelem) sx[(j >> 5) * 33 + (j & 31)] = x[gbase + j];
    }
    __syncthreads();

    const bool act = (base + t) < N;
    float xr[FD];
    if (act) {
        #pragma unroll
        for (int i = 0; i < FD; i++) xr[i] = sx[t * 33 + i];
    }
    __syncthreads();

    // stage acc tile, coalesced
    #pragma unroll
    for (int k = 0; k < 32; k++) {
        int j = k * 256 + t;
        if (j < nelem) sx[(j >> 5) * 33 + (j & 31)] = acc[gbase + j];
    }
    __syncthreads();

    unsigned long long o2[FD / 2];
    if (act) {
        #pragma unroll
        for (int j = 0; j < FD / 2; j++)
            o2[j] = pack2(sx[t * 33 + 2 * j]     + sb[2 * j],
                          sx[t * 33 + 2 * j + 1] + sb[2 * j + 1]);

        const unsigned long long* sW64 = (const unsigned long long*)sW;
        #pragma unroll 4
        for (int i = 0; i < FD; i++) {
            unsigned long long xs = pack2(xr[i], xr[i]);
            #pragma unroll
            for (int j = 0; j < FD / 2; j++)
                o2[j] = fma2(xs, sW64[i * 16 + j], o2[j]);
        }
    }
    __syncthreads();

    if (act) {
        #pragma unroll
        for (int j = 0; j < FD / 2; j++) {
            float2 v = unpack2(o2[j]);
            sx[t * 33 + 2 * j]     = sigmoidf(v.x);
            sx[t * 33 + 2 * j + 1] = sigmoidf(v.y);
        }
    }
    __syncthreads();

    // store back, coalesced
    #pragma unroll
    for (int k = 0; k < 32; k++) {
        int j = k * 256 + t;
        if (j < nelem) acc[gbase + j] = sx[(j >> 5) * 33 + (j & 31)];
    }
}

// ---------------------------------------------------------------------------
// Layer-2 edge kernel (f_out = 1), warp per edge:
//   c_i = bm2[i] + sum_a e[a]*Wm2[a,i];  s = sum_i h_org[src,i]*c_i;  acc2[dst] += s
// ---------------------------------------------------------------------------
__global__ __launch_bounds__(256) void edge2_kernel(
    const int*   __restrict__ src,
    const int*   __restrict__ dst,
    const float* __restrict__ eattr,
    const float* __restrict__ Wm2,
    const float* __restrict__ bm2)
{
    __shared__ float sW[EAD * FD];   // 256 floats
    __shared__ float sb[FD];

    const int t = threadIdx.x;
    if (t < 64) ((float4*)sW)[t] = ((const float4*)Wm2)[t];
    if (t < FD) sb[t] = bm2[t];
    __syncthreads();

    const int e = (blockIdx.x * 256 + t) >> 5;
    const int lane = t & 31;
    if (e >= NE) return;

    float ev = (lane < EAD) ? eattr[e * EAD + lane] : 0.f;
    float c = sb[lane];
    #pragma unroll
    for (int a = 0; a < EAD; a++)
        c = fmaf(__shfl_sync(0xffffffffu, ev, a), sW[a * FD + lane], c);

    int s = src[e];
    float p = g_acc_o[s * FD + lane] * c;   // g_acc_o now holds h_org
    #pragma unroll
    for (int off = 16; off; off >>= 1)
        p += __shfl_down_sync(0xffffffffu, p, off);

    if (lane == 0)
        atomicAdd(&g_acc2[dst[e]], p);
}

// ---------------------------------------------------------------------------
// Output: out[n] = sigmoid(acc2[n] + h_indivi[n,:] @ Wr2 + b2)   (warp per node)
// ---------------------------------------------------------------------------
__global__ __launch_bounds__(256) void out_kernel(
    const float* __restrict__ Wr2,
    const float* __restrict__ b2,
    float* __restrict__ out)
{
    const int t = threadIdx.x;
    const int n = (blockIdx.x * 256 + t) >> 5;
    const int lane = t & 31;
    if (n >= N_I) return;

    float p = g_acc_i[n * FD + lane] * __ldg(&Wr2[lane]);   // g_acc_i holds h_indivi
    #pragma unroll
    for (int off = 16; off; off >>= 1)
        p += __shfl_down_sync(0xffffffffu, p, off);

    if (lane == 0)
        out[n] = sigmoidf(p + g_acc2[n] + __ldg(&b2[0]));
}

// ---------------------------------------------------------------------------
extern "C" void kernel_launch(void* const* d_in, const int* in_sizes, int n_in,
                              void* d_out, int out_size)
{
    const float* x_indivi = (const float*)d_in[0];
    const float* x_org    = (const float*)d_in[1];
    const int*   src_oi   = (const int*)  d_in[2];
    const int*   dst_oi   = (const int*)  d_in[3];
    const float* ea_oi    = (const float*)d_in[4];
    const int*   src_io   = (const int*)  d_in[5];
    const int*   dst_io   = (const int*)  d_in[6];
    const float* ea_io    = (const float*)d_in[7];
    const float* Wm_oi    = (const float*)d_in[8];
    const float* bm_oi    = (const float*)d_in[9];
    const float* Wr_oi    = (const float*)d_in[10];
    const float* b_oi     = (const float*)d_in[11];
    const float* Wm_io    = (const float*)d_in[12];
    const float* bm_io    = (const float*)d_in[13];
    const float* Wr_io    = (const float*)d_in[14];
    const float* b_io     = (const float*)d_in[15];
    const float* Wm2      = (const float*)d_in[16];
    const float* bm2      = (const float*)d_in[17];
    const float* Wr2      = (const float*)d_in[18];
    const float* b2       = (const float*)d_in[19];
    float* out = (float*)d_out;

    zero_kernel<<<512, 256>>>();
    // rel0 (org->indivi): src=x_org, acc=g_acc_i. rel1 (indivi->org): src=x_indivi, acc=g_acc_o.
    edge_msg_fused<<<2 * EDGE_BLK_PER_REL, 256>>>(
        x_org,    src_oi, dst_oi, ea_oi, Wm_oi, bm_oi,
        x_indivi, src_io, dst_io, ea_io, Wm_io, bm_io);
    root_fused<<<ROOT_BLK_I + ROOT_BLK_O, 256>>>(
        x_indivi, Wr_oi, b_oi, x_org, Wr_io, b_io);
    edge2_kernel<<<(NE * 32 + 255) / 256, 256>>>(src_oi, dst_oi, ea_oi, Wm2, bm2);
    out_kernel<<<(N_I * 32 + 255) / 256, 256>>>(Wr2, b2, out);
}

// round 4
// speedup vs baseline: 1.1656x; 1.1656x over previous
#include <cuda_runtime.h>
#include <math.h>

#define N_I 100000
#define N_O 50000
#define FD 32
#define EAD 8
#define NE 100000

// Scratch (allocation-free): accumulators, reused in-place as h after root+sigmoid.
__device__ __align__(16) float g_acc_i[N_I * FD];   // layer-1 indivi agg -> h_indivi
__device__ __align__(16) float g_acc_o[N_O * FD];   // layer-1 org agg    -> h_org
__device__ __align__(16) float g_acc2[N_I];         // layer-2 agg

__device__ __forceinline__ float sigmoidf(float v) {
    return 1.0f / (1.0f + expf(-v));
}

// ---------------------------------------------------------------------------
// Zero all accumulators (float4 grid-stride)
// ---------------------------------------------------------------------------
__global__ void zero_kernel() {
    const float4 z = make_float4(0.f, 0.f, 0.f, 0.f);
    int idx = blockIdx.x * blockDim.x + threadIdx.x;
    int stride = gridDim.x * blockDim.x;
    for (int i = idx; i < N_I * FD / 4; i += stride) ((float4*)g_acc_i)[i] = z;
    for (int i = idx; i < N_O * FD / 4; i += stride) ((float4*)g_acc_o)[i] = z;
    for (int i = idx; i < N_I / 4;      i += stride) ((float4*)g_acc2)[i] = z;
}

// ---------------------------------------------------------------------------
// Layer-1 edge kernel (R1-proven scalar body), both relations in one grid:
//   msg[e,o] = sum_i x_src[src[e],i] * (bm[i,o] + sum_a e[a]*Wm[a,i,o])
// One warp handles U=4 edges; lane = output channel o.
// Wm (8x1024) + bm (1024) staged in shared; 9 LDS amortized over 36 FMA per i.
// ---------------------------------------------------------------------------
#define EDGE_BLK_PER_REL 3125   // 100000 edges / (8 warps * 4 edges)

__global__ __launch_bounds__(256) void edge_msg_fused(
    const float* __restrict__ xA, const int* __restrict__ srcA,
    const int* __restrict__ dstA, const float* __restrict__ eaA,
    const float* __restrict__ WmA, const float* __restrict__ bmA,
    const float* __restrict__ xB, const int* __restrict__ srcB,
    const int* __restrict__ dstB, const float* __restrict__ eaB,
    const float* __restrict__ WmB, const float* __restrict__ bmB)
{
    __shared__ float sWm[EAD * FD * FD];   // 32 KB
    __shared__ float sbm[FD * FD];         // 4 KB

    const int rel = (blockIdx.x >= EDGE_BLK_PER_REL) ? 1 : 0;
    const int blk = blockIdx.x - rel * EDGE_BLK_PER_REL;

    const float* __restrict__ x   = rel ? xB   : xA;
    const int*   __restrict__ src = rel ? srcB : srcA;
    const int*   __restrict__ dst = rel ? dstB : dstA;
    const float* __restrict__ ea  = rel ? eaB  : eaA;
    const float* __restrict__ Wm  = rel ? WmB  : WmA;
    const float* __restrict__ bm  = rel ? bmB  : bmA;
    float* acc = rel ? g_acc_o : g_acc_i;

    const int t = threadIdx.x;
    #pragma unroll
    for (int k = 0; k < 8; k++)
        ((float4*)sWm)[t + k * 256] = ((const float4*)Wm)[t + k * 256];
    ((float4*)sbm)[t] = ((const float4*)bm)[t];
    __syncthreads();

    const int lane = t & 31;
    const int warp = t >> 5;
    const int U = 4;
    const int e0 = (blk * 8 + warp) * U;
    if (e0 >= NE) return;

    float xreg[U];
    float er[U][EAD];
    float msg[U];
    int   dsts[U];

    #pragma unroll
    for (int u = 0; u < U; u++) {
        int e = e0 + u;
        bool valid = (e < NE);
        int s = valid ? src[e] : 0;
        dsts[u] = valid ? dst[e] : -1;
        xreg[u] = x[s * FD + lane];                    // coalesced 128B row
        float ev = (valid && lane < EAD) ? ea[e * EAD + lane] : 0.f;
        #pragma unroll
        for (int a = 0; a < EAD; a++)
            er[u][a] = __shfl_sync(0xffffffffu, ev, a);
        msg[u] = 0.f;
    }

    #pragma unroll 4
    for (int i = 0; i < FD; i++) {
        float bmv = sbm[i * FD + lane];
        float xb[U], w[U];
        #pragma unroll
        for (int u = 0; u < U; u++) {
            xb[u] = __shfl_sync(0xffffffffu, xreg[u], i);
            w[u]  = bmv;
        }
        #pragma unroll
        for (int a = 0; a < EAD; a++) {
            float wmv = sWm[a * (FD * FD) + i * FD + lane];
            #pragma unroll
            for (int u = 0; u < U; u++)
                w[u] = fmaf(er[u][a], wmv, w[u]);
        }
        #pragma unroll
        for (int u = 0; u < U; u++)
            msg[u] = fmaf(xb[u], w[u], msg[u]);
    }

    #pragma unroll
    for (int u = 0; u < U; u++)
        if (dsts[u] >= 0)
            atomicAdd(&acc[dsts[u] * FD + lane], msg[u]);
}

// ---------------------------------------------------------------------------
// Fused root kernel (both node types), scalar FMA + coalesced smem staging:
//   acc[n,:] = sigmoid(acc[n,:] + x[n,:] @ Wr + b)
// ---------------------------------------------------------------------------
#define ROOT_BLK_I ((N_I + 255) / 256)   // 391
#define ROOT_BLK_O ((N_O + 255) / 256)   // 196

__global__ __launch_bounds__(256) void root_fused(
    const float* __restrict__ xI, const float* __restrict__ WrI, const float* __restrict__ bI,
    const float* __restrict__ xO, const float* __restrict__ WrO, const float* __restrict__ bO)
{
    __shared__ float sW[FD * FD];      // 4 KB
    __shared__ float sb[FD];
    __shared__ float sx[256 * 33];     // 33.8 KB staging (pad 33 -> conflict-free)

    const int rel = (blockIdx.x >= ROOT_BLK_I) ? 1 : 0;
    const float* __restrict__ x  = rel ? xO  : xI;
    const float* __restrict__ Wr = rel ? WrO : WrI;
    const float* __restrict__ b  = rel ? bO  : bI;
    float* acc = rel ? g_acc_o : g_acc_i;
    const int N = rel ? N_O : N_I;
    const int base = (rel ? (blockIdx.x - ROOT_BLK_I) : blockIdx.x) * 256;

    const int t = threadIdx.x;
    ((float4*)sW)[t] = ((const float4*)Wr)[t];
    if (t < FD) sb[t] = b[t];

    const int nelem = min(256, N - base) * FD;   // valid floats in this tile
    const size_t gbase = (size_t)base * FD;

    // stage x tile, coalesced
    #pragma unroll
    for (int k = 0; k < 32; k++) {
        int j = k * 256 + t;
        if (j < nelem) sx[(j >> 5) * 33 + (j & 31)] = x[gbase + j];
    }
    __syncthreads();

    const bool act = (base + t) < N;
    float xr[FD];
    if (act) {
        #pragma unroll
        for (int i = 0; i < FD; i++) xr[i] = sx[t * 33 + i];
    }
    __syncthreads();

    // stage acc tile, coalesced
    #pragma unroll
    for (int k = 0; k < 32; k++) {
        int j = k * 256 + t;
        if (j < nelem) sx[(j >> 5) * 33 + (j & 31)] = acc[gbase + j];
    }
    __syncthreads();

    float o[FD];
    if (act) {
        #pragma unroll
        for (int j = 0; j < FD; j++)
            o[j] = sx[t * 33 + j] + sb[j];
        #pragma unroll 4
        for (int i = 0; i < FD; i++) {
            float xv = xr[i];
            #pragma unroll
            for (int j = 0; j < FD; j++)
                o[j] = fmaf(xv, sW[i * FD + j], o[j]);
        }
    }
    __syncthreads();

    if (act) {
        #pragma unroll
        for (int j = 0; j < FD; j++)
            sx[t * 33 + j] = sigmoidf(o[j]);
    }
    __syncthreads();

    // store back, coalesced
    #pragma unroll
    for (int k = 0; k < 32; k++) {
        int j = k * 256 + t;
        if (j < nelem) acc[gbase + j] = sx[(j >> 5) * 33 + (j & 31)];
    }
}

// ---------------------------------------------------------------------------
// Layer-2 edge kernel (f_out = 1), 4 edges per warp (octet per edge):
//   c_i = bm2[i] + sum_a e[a]*Wm2[a,i];  s = sum_i h_org[src,i]*c_i;  acc2[dst] += s
// lane = 8*(edge sub-id) + q; octet q covers channels 4q..4q+3 via float4.
// ---------------------------------------------------------------------------
__global__ __launch_bounds__(256) void edge2_kernel(
    const int*   __restrict__ src,
    const int*   __restrict__ dst,
    const float* __restrict__ eattr,
    const float* __restrict__ Wm2,
    const float* __restrict__ bm2)
{
    __shared__ float4 sW4[EAD * 8];   // [a][q] quads of Wm2 (natural layout)
    __shared__ float4 sb4[8];

    const int t = threadIdx.x;
    if (t < EAD * 8) sW4[t] = ((const float4*)Wm2)[t];
    if (t < 8)       sb4[t] = ((const float4*)bm2)[t];
    __syncthreads();

    const int gwarp = (blockIdx.x * 256 + t) >> 5;
    const int lane  = t & 31;
    const int q     = lane & 7;           // quad id within edge
    const int e     = gwarp * 4 + (lane >> 3);
    if (e >= NE) return;

    const int s = src[e];
    const float4 h4 = ((const float4*)g_acc_o)[s * 8 + q];   // h_org row, coalesced
    const float4 ea0 = ((const float4*)eattr)[e * 2 + 0];    // broadcast within octet
    const float4 ea1 = ((const float4*)eattr)[e * 2 + 1];
    const float eav[EAD] = {ea0.x, ea0.y, ea0.z, ea0.w, ea1.x, ea1.y, ea1.z, ea1.w};

    float4 c = sb4[q];
    #pragma unroll
    for (int a = 0; a < EAD; a++) {
        const float4 w = sW4[a * 8 + q];
        c.x = fmaf(eav[a], w.x, c.x);
        c.y = fmaf(eav[a], w.y, c.y);
        c.z = fmaf(eav[a], w.z, c.z);
        c.w = fmaf(eav[a], w.w, c.w);
    }

    float p = h4.x * c.x + h4.y * c.y + h4.z * c.z + h4.w * c.w;
    p += __shfl_down_sync(0xffffffffu, p, 4, 8);
    p += __shfl_down_sync(0xffffffffu, p, 2, 8);
    p += __shfl_down_sync(0xffffffffu, p, 1, 8);

    if (q == 0)
        atomicAdd(&g_acc2[dst[e]], p);
}

// ---------------------------------------------------------------------------
// Output: out[n] = sigmoid(acc2[n] + h_indivi[n,:] @ Wr2 + b2)   (warp per node)
// ---------------------------------------------------------------------------
__global__ __launch_bounds__(256) void out_kernel(
    const float* __restrict__ Wr2,
    const float* __restrict__ b2,
    float* __restrict__ out)
{
    const int t = threadIdx.x;
    const int n = (blockIdx.x * 256 + t) >> 5;
    const int lane = t & 31;
    if (n >= N_I) return;

    float p = g_acc_i[n * FD + lane] * __ldg(&Wr2[lane]);   // g_acc_i holds h_indivi
    #pragma unroll
    for (int off = 16; off; off >>= 1)
        p += __shfl_down_sync(0xffffffffu, p, off);

    if (lane == 0)
        out[n] = sigmoidf(p + g_acc2[n] + __ldg(&b2[0]));
}

// ---------------------------------------------------------------------------
extern "C" void kernel_launch(void* const* d_in, const int* in_sizes, int n_in,
                              void* d_out, int out_size)
{
    const float* x_indivi = (const float*)d_in[0];
    const float* x_org    = (const float*)d_in[1];
    const int*   src_oi   = (const int*)  d_in[2];
    const int*   dst_oi   = (const int*)  d_in[3];
    const float* ea_oi    = (const float*)d_in[4];
    const int*   src_io   = (const int*)  d_in[5];
    const int*   dst_io   = (const int*)  d_in[6];
    const float* ea_io    = (const float*)d_in[7];
    const float* Wm_oi    = (const float*)d_in[8];
    const float* bm_oi    = (const float*)d_in[9];
    const float* Wr_oi    = (const float*)d_in[10];
    const float* b_oi     = (const float*)d_in[11];
    const float* Wm_io    = (const float*)d_in[12];
    const float* bm_io    = (const float*)d_in[13];
    const float* Wr_io    = (const float*)d_in[14];
    const float* b_io     = (const float*)d_in[15];
    const float* Wm2      = (const float*)d_in[16];
    const float* bm2      = (const float*)d_in[17];
    const float* Wr2      = (const float*)d_in[18];
    const float* b2       = (const float*)d_in[19];
    float* out = (float*)d_out;

    zero_kernel<<<512, 256>>>();
    // rel0 (org->indivi): src=x_org, acc=g_acc_i. rel1 (indivi->org): src=x_indivi, acc=g_acc_o.
    edge_msg_fused<<<2 * EDGE_BLK_PER_REL, 256>>>(
        x_org,    src_oi, dst_oi, ea_oi, Wm_oi, bm_oi,
        x_indivi, src_io, dst_io, ea_io, Wm_io, bm_io);
    root_fused<<<ROOT_BLK_I + ROOT_BLK_O, 256>>>(
        x_indivi, Wr_oi, b_oi, x_org, Wr_io, b_io);
    edge2_kernel<<<(NE + 4 * 8 - 1) / (4 * 8), 256>>>(src_oi, dst_oi, ea_oi, Wm2, bm2);
    out_kernel<<<(N_I * 32 + 255) / 256, 256>>>(Wr2, b2, out);
}

// round 6
// speedup vs baseline: 1.9926x; 1.7095x over previous
#include <cuda_runtime.h>
#include <math.h>
#include <stdint.h>

#define N_I 100000
#define N_O 50000
#define FD 32
#define EAD 8
#define NE 100000

// Scratch (allocation-free): accumulators, reused in-place as h after root+sigmoid.
__device__ __align__(16) float g_acc_i[N_I * FD];   // layer-1 indivi agg -> h_indivi
__device__ __align__(16) float g_acc_o[N_O * FD];   // layer-1 org agg    -> h_org
__device__ __align__(16) float g_acc2[N_I];         // layer-2 agg

__device__ __forceinline__ float sigmoidf(float v) {
    return 1.0f / (1.0f + expf(-v));
}

__device__ __forceinline__ uint32_t f2tf32(float v) {
    uint32_t r;
    asm("cvt.rna.tf32.f32 %0, %1;" : "=r"(r) : "f"(v));
    return r;
}

// m16n8k8 tf32 HMMA (base-target PTX, works under compute_103).
// D(16x8) += A(16x8,row) * B(8x8,col).
__device__ __forceinline__ void mma16n8k8(float* d, const uint32_t* a,
                                          uint32_t b0, uint32_t b1) {
    asm volatile(
        "mma.sync.aligned.m16n8k8.row.col.f32.tf32.tf32.f32 "
        "{%0,%1,%2,%3}, {%4,%5,%6,%7}, {%8,%9}, {%0,%1,%2,%3};"
        : "+f"(d[0]), "+f"(d[1]), "+f"(d[2]), "+f"(d[3])
        : "r"(a[0]), "r"(a[1]), "r"(a[2]), "r"(a[3]), "r"(b0), "r"(b1));
}

// ---------------------------------------------------------------------------
// Zero all accumulators (float4 grid-stride)
// ---------------------------------------------------------------------------
__global__ void zero_kernel() {
    const float4 z = make_float4(0.f, 0.f, 0.f, 0.f);
    int idx = blockIdx.x * blockDim.x + threadIdx.x;
    int stride = gridDim.x * blockDim.x;
    for (int i = idx; i < N_I * FD / 4; i += stride) ((float4*)g_acc_i)[i] = z;
    for (int i = idx; i < N_O * FD / 4; i += stride) ((float4*)g_acc_o)[i] = z;
    for (int i = idx; i < N_I / 4;      i += stride) ((float4*)g_acc2)[i] = z;
}

// ---------------------------------------------------------------------------
// Layer-1 edge kernel via mma.sync tf32.
//   msg[e,o] = sum_c s_c[e] * (x[src[e],:] @ Wc)[o],  s_0=1 (bm), s_{1+a}=ea[e,a]
// CTA = 256 thr (8 warps), 1024 edges. Warp handles 4 pairs of m16 strips
// (32 edges per pair). W' (288x32) staged once per CTA in tf32, stride-40
// padding -> conflict-free A and B fragment LDS. Per-chunk fp32 accumulators
// combined with fp32 scales (exact); only x/W rounded to tf32 (RNA).
// Epilogue: shfl-pair exchange -> one float4 atomicAdd per thread per n-tile.
// ---------------------------------------------------------------------------
#define ECTA 1024
#define EDGE_CTAS_PER_REL ((NE + ECTA - 1) / ECTA)   // 98

#define SW_STRIDE 40
#define SW_BYTES  (288 * SW_STRIDE * 4)              // 46080
#define SX_BYTES  (32 * SW_STRIDE * 4)               // 5120 per warp
#define SSC_STRIDE 12
#define SSC_BYTES (32 * SSC_STRIDE * 4)              // 1536 per warp
#define SX_OFF    SW_BYTES
#define SSC_OFF   (SW_BYTES + 8 * SX_BYTES)          // 87040
#define SMEM_DYN  (SSC_OFF + 8 * SSC_BYTES)          // 99328

__global__ __launch_bounds__(256) void edge_mma_kernel(
    const float* __restrict__ xA, const int* __restrict__ srcA,
    const int* __restrict__ dstA, const float* __restrict__ eaA,
    const float* __restrict__ WmA, const float* __restrict__ bmA,
    const float* __restrict__ xB, const int* __restrict__ srcB,
    const int* __restrict__ dstB, const float* __restrict__ eaB,
    const float* __restrict__ WmB, const float* __restrict__ bmB)
{
    extern __shared__ char smem[];
    uint32_t* sW = (uint32_t*)smem;                      // [288][40] tf32

    const int rel  = (blockIdx.x >= EDGE_CTAS_PER_REL) ? 1 : 0;
    const int tile = blockIdx.x - rel * EDGE_CTAS_PER_REL;

    const float* __restrict__ x   = rel ? xB   : xA;
    const int*   __restrict__ src = rel ? srcB : srcA;
    const int*   __restrict__ dst = rel ? dstB : dstA;
    const float* __restrict__ ea  = rel ? eaB  : eaA;
    const float* __restrict__ Wm  = rel ? WmB  : WmA;
    const float* __restrict__ bm  = rel ? bmB  : bmA;
    float* acc = rel ? g_acc_o : g_acc_i;

    const int t = threadIdx.x;
    const int warp = t >> 5;
    const int lane = t & 31;
    const int g   = lane >> 2;   // fragment row group 0..7
    const int tig = lane & 3;    // thread-in-group 0..3

    // ---- stage W' = [bm ; Wm] as tf32, k=0..287, n=0..31, stride 40 ----
    for (int idx = t; idx < 288 * 32; idx += 256) {
        int k = idx >> 5, n = idx & 31;
        float v = (idx < 1024) ? bm[idx] : Wm[idx - 1024];
        sW[k * SW_STRIDE + n] = f2tf32(v);
    }
    __syncthreads();

    uint32_t* sx  = (uint32_t*)(smem + SX_OFF  + warp * SX_BYTES);   // [32][40]
    float*    ssc = (float*)   (smem + SSC_OFF + warp * SSC_BYTES);  // [32][12]

    const int cta_e0 = tile * ECTA;

    for (int pp = 0; pp < 4; pp++) {
        const int e0 = cta_e0 + warp * 128 + pp * 32;
        const int e_l = e0 + lane;
        const bool v_l = (e_l < NE);
        const int src_l = v_l ? src[e_l] : 0;
        const int dst_l = v_l ? dst[e_l] : -1;

        __syncwarp();
        // stage x rows (tf32): row r = edge offset, col = lane (coalesced 128B)
        for (int r = 0; r < 32; r++) {
            int s_r = __shfl_sync(0xffffffffu, src_l, r);
            sx[r * SW_STRIDE + lane] = f2tf32(x[s_r * FD + lane]);
        }
        // stage scales: ssc[r][0]=1, ssc[r][1+a]=ea[r][a]
        {
            float4 q0, q1;
            if (v_l) {
                q0 = ((const float4*)ea)[e_l * 2 + 0];
                q1 = ((const float4*)ea)[e_l * 2 + 1];
            } else {
                q0 = q1 = make_float4(0.f, 0.f, 0.f, 0.f);
            }
            float* sr = ssc + lane * SSC_STRIDE;
            sr[0] = 1.0f;
            sr[1] = q0.x; sr[2] = q0.y; sr[3] = q0.z; sr[4] = q0.w;
            sr[5] = q1.x; sr[6] = q1.y; sr[7] = q1.z; sr[8] = q1.w;
        }
        __syncwarp();

        // ---- A fragments for both strips (rows 0-15 and 16-31) ----
        uint32_t A0[4][4], A1[4][4];
        #pragma unroll
        for (int ks = 0; ks < 4; ks++) {
            int c0 = ks * 8 + tig, c1 = ks * 8 + tig + 4;
            A0[ks][0] = sx[(g)      * SW_STRIDE + c0];
            A0[ks][1] = sx[(g + 8)  * SW_STRIDE + c0];
            A0[ks][2] = sx[(g)      * SW_STRIDE + c1];
            A0[ks][3] = sx[(g + 8)  * SW_STRIDE + c1];
            A1[ks][0] = sx[(g + 16) * SW_STRIDE + c0];
            A1[ks][1] = sx[(g + 24) * SW_STRIDE + c0];
            A1[ks][2] = sx[(g + 16) * SW_STRIDE + c1];
            A1[ks][3] = sx[(g + 24) * SW_STRIDE + c1];
        }
        const int dl0 = __shfl_sync(0xffffffffu, dst_l, g);
        const int dh0 = __shfl_sync(0xffffffffu, dst_l, g + 8);
        const int dl1 = __shfl_sync(0xffffffffu, dst_l, g + 16);
        const int dh1 = __shfl_sync(0xffffffffu, dst_l, g + 24);

        #pragma unroll
        for (int nt = 0; nt < 4; nt++) {
            float m0[4] = {0.f, 0.f, 0.f, 0.f};
            float m1[4] = {0.f, 0.f, 0.f, 0.f};
            const int nb = nt * 8 + g;

            #pragma unroll
            for (int c = 0; c < 9; c++) {
                float t0[4] = {0.f, 0.f, 0.f, 0.f};
                float t1[4] = {0.f, 0.f, 0.f, 0.f};
                #pragma unroll
                for (int ks = 0; ks < 4; ks++) {
                    const int kb = c * 32 + ks * 8 + tig;
                    uint32_t b0 = sW[(kb)     * SW_STRIDE + nb];
                    uint32_t b1 = sW[(kb + 4) * SW_STRIDE + nb];
                    mma16n8k8(t0, A0[ks], b0, b1);
                    mma16n8k8(t1, A1[ks], b0, b1);
                }
                const float sl0 = ssc[(g)      * SSC_STRIDE + c];
                const float sh0 = ssc[(g + 8)  * SSC_STRIDE + c];
                const float sl1 = ssc[(g + 16) * SSC_STRIDE + c];
                const float sh1 = ssc[(g + 24) * SSC_STRIDE + c];
                m0[0] = fmaf(sl0, t0[0], m0[0]);
                m0[1] = fmaf(sl0, t0[1], m0[1]);
                m0[2] = fmaf(sh0, t0[2], m0[2]);
                m0[3] = fmaf(sh0, t0[3], m0[3]);
                m1[0] = fmaf(sl1, t1[0], m1[0]);
                m1[1] = fmaf(sl1, t1[1], m1[1]);
                m1[2] = fmaf(sh1, t1[2], m1[2]);
                m1[3] = fmaf(sh1, t1[3], m1[3]);
            }

            // epilogue: pair-exchange -> one float4 RED per thread per strip
            const int colb = nt * 8 + 2 * (tig & ~1);
            const bool odd = (tig & 1);
            {
                float s0 = __shfl_xor_sync(0xffffffffu, odd ? m0[0] : m0[2], 1);
                float s1 = __shfl_xor_sync(0xffffffffu, odd ? m0[1] : m0[3], 1);
                int drow = odd ? dh0 : dl0;
                float4 val = odd ? make_float4(s0, s1, m0[2], m0[3])
                                 : make_float4(m0[0], m0[1], s0, s1);
                if (drow >= 0)
                    atomicAdd((float4*)(acc + (size_t)drow * FD + colb), val);
            }
            {
                float s0 = __shfl_xor_sync(0xffffffffu, odd ? m1[0] : m1[2], 1);
                float s1 = __shfl_xor_sync(0xffffffffu, odd ? m1[1] : m1[3], 1);
                int drow = odd ? dh1 : dl1;
                float4 val = odd ? make_float4(s0, s1, m1[2], m1[3])
                                 : make_float4(m1[0], m1[1], s0, s1);
                if (drow >= 0)
                    atomicAdd((float4*)(acc + (size_t)drow * FD + colb), val);
            }
        }
        __syncwarp();
    }
}

// ---------------------------------------------------------------------------
// Fused root kernel (both node types), scalar FMA + coalesced smem staging:
//   acc[n,:] = sigmoid(acc[n,:] + x[n,:] @ Wr + b)
// ---------------------------------------------------------------------------
#define ROOT_BLK_I ((N_I + 255) / 256)   // 391
#define ROOT_BLK_O ((N_O + 255) / 256)   // 196

__global__ __launch_bounds__(256) void root_fused(
    const float* __restrict__ xI, const float* __restrict__ WrI, const float* __restrict__ bI,
    const float* __restrict__ xO, const float* __restrict__ WrO, const float* __restrict__ bO)
{
    __shared__ float sW[FD * FD];
    __shared__ float sb[FD];
    __shared__ float sx[256 * 33];

    const int rel = (blockIdx.x >= ROOT_BLK_I) ? 1 : 0;
    const float* __restrict__ x  = rel ? xO  : xI;
    const float* __restrict__ Wr = rel ? WrO : WrI;
    const float* __restrict__ b  = rel ? bO  : bI;
    float* acc = rel ? g_acc_o : g_acc_i;
    const int N = rel ? N_O : N_I;
    const int base = (rel ? (blockIdx.x - ROOT_BLK_I) : blockIdx.x) * 256;

    const int t = threadIdx.x;
    ((float4*)sW)[t] = ((const float4*)Wr)[t];
    if (t < FD) sb[t] = b[t];

    const int nelem = min(256, N - base) * FD;
    const size_t gbase = (size_t)base * FD;

    #pragma unroll
    for (int k = 0; k < 32; k++) {
        int j = k * 256 + t;
        if (j < nelem) sx[(j >> 5) * 33 + (j & 31)] = x[gbase + j];
    }
    __syncthreads();

    const bool act = (base + t) < N;
    float xr[FD];
    if (act) {
        #pragma unroll
        for (int i = 0; i < FD; i++) xr[i] = sx[t * 33 + i];
    }
    __syncthreads();

    #pragma unroll
    for (int k = 0; k < 32; k++) {
        int j = k * 256 + t;
        if (j < nelem) sx[(j >> 5) * 33 + (j & 31)] = acc[gbase + j];
    }
    __syncthreads();

    float o[FD];
    if (act) {
        #pragma unroll
        for (int j = 0; j < FD; j++)
            o[j] = sx[t * 33 + j] + sb[j];
        #pragma unroll 4
        for (int i = 0; i < FD; i++) {
            float xv = xr[i];
            #pragma unroll
            for (int j = 0; j < FD; j++)
                o[j] = fmaf(xv, sW[i * FD + j], o[j]);
        }
    }
    __syncthreads();

    if (act) {
        #pragma unroll
        for (int j = 0; j < FD; j++)
            sx[t * 33 + j] = sigmoidf(o[j]);
    }
    __syncthreads();

    #pragma unroll
    for (int k = 0; k < 32; k++) {
        int j = k * 256 + t;
        if (j < nelem) acc[gbase + j] = sx[(j >> 5) * 33 + (j & 31)];
    }
}

// ---------------------------------------------------------------------------
// Layer-2 edge kernel (f_out = 1), 4 edges per warp (octet per edge)
// ---------------------------------------------------------------------------
__global__ __launch_bounds__(256) void edge2_kernel(
    const int*   __restrict__ src,
    const int*   __restrict__ dst,
    const float* __restrict__ eattr,
    const float* __restrict__ Wm2,
    const float* __restrict__ bm2)
{
    __shared__ float4 sW4[EAD * 8];
    __shared__ float4 sb4[8];

    const int t = threadIdx.x;
    if (t < EAD * 8) sW4[t] = ((const float4*)Wm2)[t];
    if (t < 8)       sb4[t] = ((const float4*)bm2)[t];
    __syncthreads();

    const int gwarp = (blockIdx.x * 256 + t) >> 5;
    const int lane  = t & 31;
    const int q     = lane & 7;
    const int e     = gwarp * 4 + (lane >> 3);
    if (e >= NE) return;

    const int s = src[e];
    const float4 h4 = ((const float4*)g_acc_o)[s * 8 + q];
    const float4 ea0 = ((const float4*)eattr)[e * 2 + 0];
    const float4 ea1 = ((const float4*)eattr)[e * 2 + 1];
    const float eav[EAD] = {ea0.x, ea0.y, ea0.z, ea0.w, ea1.x, ea1.y, ea1.z, ea1.w};

    float4 c = sb4[q];
    #pragma unroll
    for (int a = 0; a < EAD; a++) {
        const float4 w = sW4[a * 8 + q];
        c.x = fmaf(eav[a], w.x, c.x);
        c.y = fmaf(eav[a], w.y, c.y);
        c.z = fmaf(eav[a], w.z, c.z);
        c.w = fmaf(eav[a], w.w, c.w);
    }

    float p = h4.x * c.x + h4.y * c.y + h4.z * c.z + h4.w * c.w;
    p += __shfl_down_sync(0xffffffffu, p, 4, 8);
    p += __shfl_down_sync(0xffffffffu, p, 2, 8);
    p += __shfl_down_sync(0xffffffffu, p, 1, 8);

    if (q == 0)
        atomicAdd(&g_acc2[dst[e]], p);
}

// ---------------------------------------------------------------------------
// Output: out[n] = sigmoid(acc2[n] + h_indivi[n,:] @ Wr2 + b2)   (warp per node)
// ---------------------------------------------------------------------------
__global__ __launch_bounds__(256) void out_kernel(
    const float* __restrict__ Wr2,
    const float* __restrict__ b2,
    float* __restrict__ out)
{
    const int t = threadIdx.x;
    const int n = (blockIdx.x * 256 + t) >> 5;
    const int lane = t & 31;
    if (n >= N_I) return;

    float p = g_acc_i[n * FD + lane] * __ldg(&Wr2[lane]);
    #pragma unroll
    for (int off = 16; off; off >>= 1)
        p += __shfl_down_sync(0xffffffffu, p, off);

    if (lane == 0)
        out[n] = sigmoidf(p + g_acc2[n] + __ldg(&b2[0]));
}

// ---------------------------------------------------------------------------
extern "C" void kernel_launch(void* const* d_in, const int* in_sizes, int n_in,
                              void* d_out, int out_size)
{
    const float* x_indivi = (const float*)d_in[0];
    const float* x_org    = (const float*)d_in[1];
    const int*   src_oi   = (const int*)  d_in[2];
    const int*   dst_oi   = (const int*)  d_in[3];
    const float* ea_oi    = (const float*)d_in[4];
    const int*   src_io   = (const int*)  d_in[5];
    const int*   dst_io   = (const int*)  d_in[6];
    const float* ea_io    = (const float*)d_in[7];
    const float* Wm_oi    = (const float*)d_in[8];
    const float* bm_oi    = (const float*)d_in[9];
    const float* Wr_oi    = (const float*)d_in[10];
    const float* b_oi     = (const float*)d_in[11];
    const float* Wm_io    = (const float*)d_in[12];
    const float* bm_io    = (const float*)d_in[13];
    const float* Wr_io    = (const float*)d_in[14];
    const float* b_io     = (const float*)d_in[15];
    const float* Wm2      = (const float*)d_in[16];
    const float* bm2      = (const float*)d_in[17];
    const float* Wr2      = (const float*)d_in[18];
    const float* b2       = (const float*)d_in[19];
    float* out = (float*)d_out;

    cudaFuncSetAttribute(edge_mma_kernel,
                         cudaFuncAttributeMaxDynamicSharedMemorySize, SMEM_DYN);

    zero_kernel<<<512, 256>>>();
    // rel0 (org->indivi): src=x_org, acc=g_acc_i. rel1 (indivi->org): src=x_indivi, acc=g_acc_o.
    edge_mma_kernel<<<2 * EDGE_CTAS_PER_REL, 256, SMEM_DYN>>>(
        x_org,    src_oi, dst_oi, ea_oi, Wm_oi, bm_oi,
        x_indivi, src_io, dst_io, ea_io, Wm_io, bm_io);
    root_fused<<<ROOT_BLK_I + ROOT_BLK_O, 256>>>(
        x_indivi, Wr_oi, b_oi, x_org, Wr_io, b_io);
    edge2_kernel<<<(NE + 4 * 8 - 1) / (4 * 8), 256>>>(src_oi, dst_oi, ea_oi, Wm2, bm2);
    out_kernel<<<(N_I * 32 + 255) / 256, 256>>>(Wr2, b2, out);
}